// round 1
// baseline (speedup 1.0000x reference)
#include <cuda_runtime.h>
#include <cstdint>
#include <cstddef>

// ---------------- problem constants ----------------
#define CIN   128
#define COUT  128
#define BATCH 16
#define HW    112
#define TAPS  81    // 9x9 dilated kernel extent

// K2 layout: [tap][ci][co]  (tap = ih*9+iw), tf32-rounded fp32
__device__ float g_K2[TAPS * CIN * COUT];

__device__ __forceinline__ float tf32_rn(float x) {
    uint32_t u;
    asm("cvt.rna.tf32.f32 %0, %1;" : "=r"(u) : "f"(x));
    return __uint_as_float(u);
}

// ---------------- stage 1: build scattered kernel ----------------
// One block per ci (128 blocks), one thread per co (128 threads).
// Each thread owns its private 81-entry row in smem -> no atomics, deterministic.
__global__ void build_K(const float* __restrict__ weight, const float* __restrict__ P) {
    __shared__ float sK[128][81];
    int ci = blockIdx.x;
    int co = threadIdx.x;

    #pragma unroll
    for (int i = 0; i < 81; i++) sK[co][i] = 0.f;

    const float* P0 = P;
    const float* P1 = P + 128 * 128 * 9;

    #pragma unroll
    for (int kh = 0; kh < 3; kh++) {
        #pragma unroll
        for (int kw = 0; kw < 3; kw++) {
            int widx = ((co * 128 + ci) * 3 + kh) * 3 + kw;
            float w  = weight[widx];
            float ph = (float)(kh * 4) + P0[widx];
            float pw = (float)(kw * 4) + P1[widx];
            ph = fminf(fmaxf(ph, 0.f), 8.f);
            pw = fminf(fmaxf(pw, 0.f), 8.f);
            float fh = floorf(ph), fw = floorf(pw);
            float rh = ph - fh,    rw = pw - fw;
            int ih = (int)fh, iw = (int)fw;
            int ih1 = min(ih + 1, 8), iw1 = min(iw + 1, 8);
            sK[co][ih  * 9 + iw ] += w * (1.f - rh) * (1.f - rw);
            sK[co][ih1 * 9 + iw ] += w * rh         * (1.f - rw);
            sK[co][ih  * 9 + iw1] += w * (1.f - rh) * rw;
            sK[co][ih1 * 9 + iw1] += w * rh         * rw;
        }
    }

    // write [tap][ci][co], coalesced over co, tf32-rounded once here
    for (int i = 0; i < 81; i++)
        g_K2[(i * 128 + ci) * 128 + co] = tf32_rn(sK[co][i]);
}

// ---------------- stage 2: implicit-GEMM conv (tf32 mma.sync) ----------------
// Block tile: 64 co x 128 px (8 rows x 16 cols spatial), 256 threads = 8 warps.
// Warp tile : 32 co x 32 px (2 spatial rows x 16 cols) -> 2 m-frags x 4 n-frags.
// K loop    : ci chunks of 32 (x-tile with halo staged once, reused over all 81 taps),
//             inner 81 taps each staging a 64x32 K2 slice (double buffered).
#define CIS       36                    // ci stride in xs (32 padded to 36: bank spread)
#define XS_FLOATS (16 * 24 * CIS)       // 13824 floats
#define AS_FLOATS (2 * 2048)            // double-buffered 32ci x 64co
#define SMEM_BYTES ((XS_FLOATS + AS_FLOATS) * 4)   // 71680

__global__ __launch_bounds__(256, 2)
void dcls_gemm(const float* __restrict__ x, const float* __restrict__ bias,
               float* __restrict__ out) {
    extern __shared__ float smem[];
    float* xs = smem;                 // [pix = row*24+col][ci(CIS)]
    float* As = smem + XS_FLOATS;     // [buf][ci*64 + (co ^ ((ci&3)<<3))]

    const int tid  = threadIdx.x;
    const int lane = tid & 31;
    const int warp = tid >> 5;
    const int aci  = lane & 3;        // k-group within quad
    const int aco  = lane >> 2;       // m/n group id

    // block -> (batch, spatial tile, co tile)
    const int s   = blockIdx.x;                 // 0..1567
    const int co0 = blockIdx.y * 64;            // 0 or 64
    const int bb  = s / 98;
    const int r   = s - bb * 98;
    const int th_ = r / 7, tw_ = r - (r / 7) * 7;
    const int h0  = th_ * 8, w0 = tw_ * 16;

    const int wco = warp >> 2;        // 0..1 : co half
    const int wpx = warp & 3;         // 0..3 : pixel-row pair
    const int co_base = wco * 32;
    const int r0 = wpx * 2;

    float acc[2][4][4];
    #pragma unroll
    for (int i = 0; i < 2; i++)
        #pragma unroll
        for (int j = 0; j < 4; j++)
            #pragma unroll
            for (int k = 0; k < 4; k++) acc[i][j][k] = 0.f;

    for (int ci0 = 0; ci0 < 128; ci0 += 32) {
        __syncthreads();   // previous chunk's readers done before xs overwrite

        // ---- stage x tile (16 rows x 24 cols x 32 ci), tf32-rounded ----
        for (int idx = tid; idx < 16 * 24 * 32; idx += 256) {
            int ci  = idx / 384;
            int pix = idx - ci * 384;
            int row = pix / 24, col = pix - row * 24;
            int gh = h0 - 4 + row, gw = w0 - 4 + col;
            float v = 0.f;
            if ((unsigned)gh < 112u && (unsigned)gw < 112u)
                v = x[(((size_t)bb * 128 + ci0 + ci) * 112 + gh) * 112 + gw];
            xs[pix * CIS + ci] = tf32_rn(v);
        }
        // ---- prime As buffer 0 with tap 0 ----
        {
            const float* g = g_K2 + (size_t)ci0 * 128 + co0;
            #pragma unroll
            for (int rr = 0; rr < 8; rr++) {
                int idx = rr * 256 + tid;
                int ci = idx >> 6, co = idx & 63;
                As[ci * 64 + (co ^ ((ci & 3) << 3))] = g[ci * 128 + co];
            }
        }
        __syncthreads();

        for (int tap = 0; tap < 81; tap++) {
            const int buf = tap & 1;

            // prefetch next tap's K2 slice into registers (hides LDG under MMA)
            float nxt[8];
            if (tap < 80) {
                const float* g = g_K2 + (size_t)(tap + 1) * 16384 + (size_t)ci0 * 128 + co0;
                #pragma unroll
                for (int rr = 0; rr < 8; rr++) {
                    int idx = rr * 256 + tid;
                    nxt[rr] = g[(idx >> 6) * 128 + (idx & 63)];
                }
            }

            const int dh = tap / 9, dw = tap - dh * 9;
            const float* Ab = As + buf * 2048;
            const int xbase = ((r0 + dh) * 24 + dw) * CIS;

            #pragma unroll
            for (int kk = 0; kk < 4; kk++) {
                const int kci = kk * 8;
                uint32_t a[2][4], bf[4][2];
                #pragma unroll
                for (int i = 0; i < 2; i++) {
                    const int cb = co_base + i * 16 + aco;
                    const int c0 = (kci + aci) * 64;
                    const int c4 = (kci + aci + 4) * 64;
                    const int sw = aci << 3;
                    a[i][0] = __float_as_uint(Ab[c0 + ( cb      ^ sw)]);
                    a[i][1] = __float_as_uint(Ab[c0 + ((cb + 8) ^ sw)]);
                    a[i][2] = __float_as_uint(Ab[c4 + ( cb      ^ sw)]);
                    a[i][3] = __float_as_uint(Ab[c4 + ((cb + 8) ^ sw)]);
                }
                #pragma unroll
                for (int j = 0; j < 4; j++) {
                    const int base = xbase
                                   + (j >> 1) * 24 * CIS
                                   + ((j & 1) * 8 + aco) * CIS
                                   + kci + aci;
                    bf[j][0] = __float_as_uint(xs[base]);
                    bf[j][1] = __float_as_uint(xs[base + 4]);
                }
                #pragma unroll
                for (int i = 0; i < 2; i++)
                    #pragma unroll
                    for (int j = 0; j < 4; j++) {
                        asm volatile(
                            "mma.sync.aligned.m16n8k8.row.col.f32.tf32.tf32.f32 "
                            "{%0,%1,%2,%3}, {%4,%5,%6,%7}, {%8,%9}, {%0,%1,%2,%3};"
                            : "+f"(acc[i][j][0]), "+f"(acc[i][j][1]),
                              "+f"(acc[i][j][2]), "+f"(acc[i][j][3])
                            : "r"(a[i][0]), "r"(a[i][1]), "r"(a[i][2]), "r"(a[i][3]),
                              "r"(bf[j][0]), "r"(bf[j][1]));
                    }
            }

            if (tap < 80) {
                float* Anb = As + (buf ^ 1) * 2048;
                #pragma unroll
                for (int rr = 0; rr < 8; rr++) {
                    int idx = rr * 256 + tid;
                    int ci = idx >> 6, co = idx & 63;
                    Anb[ci * 64 + (co ^ ((ci & 3) << 3))] = nxt[rr];
                }
            }
            __syncthreads();
        }
    }

    // ---- epilogue: + bias, NCHW stores (float2, 8B-aligned) ----
    #pragma unroll
    for (int i = 0; i < 2; i++) {
        const int corow = co0 + co_base + i * 16 + aco;
        const float b0 = bias[corow];
        const float b1 = bias[corow + 8];
        #pragma unroll
        for (int j = 0; j < 4; j++) {
            const int h = h0 + r0 + (j >> 1);
            const int w = w0 + (j & 1) * 8 + 2 * aci;
            float2 v0 = make_float2(acc[i][j][0] + b0, acc[i][j][1] + b0);
            float2 v1 = make_float2(acc[i][j][2] + b1, acc[i][j][3] + b1);
            size_t o0 = (((size_t)bb * 128 + corow    ) * 112 + h) * 112 + w;
            size_t o1 = (((size_t)bb * 128 + corow + 8) * 112 + h) * 112 + w;
            *reinterpret_cast<float2*>(out + o0) = v0;
            *reinterpret_cast<float2*>(out + o1) = v1;
        }
    }
}

// ---------------- launch ----------------
extern "C" void kernel_launch(void* const* d_in, const int* in_sizes, int n_in,
                              void* d_out, int out_size) {
    const float* x      = (const float*)d_in[0];
    const float* weight = (const float*)d_in[1];
    const float* P      = (const float*)d_in[2];
    const float* bias   = (const float*)d_in[3];
    float* out = (float*)d_out;

    build_K<<<128, 128>>>(weight, P);

    cudaFuncSetAttribute(dcls_gemm, cudaFuncAttributeMaxDynamicSharedMemorySize, SMEM_BYTES);
    dim3 grid(16 * 14 * 7, 2);   // (batch*spatial tiles, co tiles)
    dcls_gemm<<<grid, 256, SMEM_BYTES>>>(x, bias, out);
}

// round 3
// speedup vs baseline: 2.4711x; 2.4711x over previous
#include <cuda_runtime.h>
#include <cuda_fp16.h>
#include <cstdint>
#include <cstddef>

// ================= problem =================
// x:(16,128,112,112)f32  weight:(128,128,3,3)  P:(2,128,128,3,3)  bias:(128)
// out:(16,128,112,112) = conv(x, scatter(weight,P) 9x9, pad 4) + bias

#define TAPS 81

// K2 as f16, layout [tap][co][ci]  (2048 uint4 = 32 KB per tap)
__device__ uint4 g_K2h4[TAPS * 2048];

__device__ __forceinline__ uint32_t smem_u32(const void* p) {
    uint32_t a;
    asm("{ .reg .u64 t; cvta.to.shared.u64 t, %1; cvt.u32.u64 %0, t; }" : "=r"(a) : "l"(p));
    return a;
}

#define LDSM4(rv, addr)                                                      \
    asm volatile("ldmatrix.sync.aligned.m8n8.x4.shared.b16 {%0,%1,%2,%3}, [%4];" \
        : "=r"((rv)[0]), "=r"((rv)[1]), "=r"((rv)[2]), "=r"((rv)[3]) : "r"(addr))

#define LDSM2(rv, addr)                                                      \
    asm volatile("ldmatrix.sync.aligned.m8n8.x2.shared.b16 {%0,%1}, [%2];"   \
        : "=r"((rv)[0]), "=r"((rv)[1]) : "r"(addr))

#define HMMA(d, a, b0, b1)                                                   \
    asm volatile("mma.sync.aligned.m16n8k16.row.col.f32.f16.f16.f32 "        \
        "{%0,%1,%2,%3}, {%4,%5,%6,%7}, {%8,%9}, {%0,%1,%2,%3};"              \
        : "+f"((d)[0]), "+f"((d)[1]), "+f"((d)[2]), "+f"((d)[3])             \
        : "r"((a)[0]), "r"((a)[1]), "r"((a)[2]), "r"((a)[3]),                \
          "r"(b0), "r"(b1))

// ================= stage 1: scatter weights -> f16 K2 =================
// block = co (128), thread = ci (128); each thread owns a private 81-row.
__global__ void build_K(const float* __restrict__ weight, const float* __restrict__ P) {
    __shared__ float sK[128][81];
    const int co = blockIdx.x;
    const int ci = threadIdx.x;

    #pragma unroll
    for (int i = 0; i < 81; i++) sK[ci][i] = 0.f;

    const float* P0 = P;
    const float* P1 = P + 128 * 128 * 9;

    #pragma unroll
    for (int kh = 0; kh < 3; kh++) {
        #pragma unroll
        for (int kw = 0; kw < 3; kw++) {
            int widx = ((co * 128 + ci) * 3 + kh) * 3 + kw;
            float w  = weight[widx];
            float ph = (float)(kh * 4) + P0[widx];
            float pw = (float)(kw * 4) + P1[widx];
            ph = fminf(fmaxf(ph, 0.f), 8.f);
            pw = fminf(fmaxf(pw, 0.f), 8.f);
            float fh = floorf(ph), fw = floorf(pw);
            float rh = ph - fh,    rw = pw - fw;
            int ih = (int)fh, iw = (int)fw;
            int ih1 = min(ih + 1, 8), iw1 = min(iw + 1, 8);
            sK[ci][ih  * 9 + iw ] += w * (1.f - rh) * (1.f - rw);
            sK[ci][ih1 * 9 + iw ] += w * rh         * (1.f - rw);
            sK[ci][ih  * 9 + iw1] += w * (1.f - rh) * rw;
            sK[ci][ih1 * 9 + iw1] += w * rh         * rw;
        }
    }
    __syncwarp();
    __half* g = (__half*)g_K2h4;
    for (int tap = 0; tap < 81; tap++)
        g[((size_t)tap * 128 + co) * 128 + ci] = __float2half_rn(sK[ci][tap]);
}

// ================= stage 2: fp16 implicit-GEMM conv =================
// Block: 256 thr = 8 warps (2 co-halves x 4 output rows). Block tile:
// co=128, px = 4 rows x 56 w. Warp tile: 64co x 56px = 4 m-frags x 7 n-frags.
// K = ci, two chunks of 64. 81 taps = descriptor-free offsets into one x tile.
//
// xs: [pix = hh*64 + wl][ci64]  f16, row stride 144 B (72 f16)  -> 110592 B
// A : [co128][ci64]             f16, row stride 144 B, x2 bufs  ->  36864 B
#define XS_STRIDE 144
#define A_OFF     110592
#define A_BYTES   18432
#define SMEM_TOTAL (A_OFF + 2 * A_BYTES)   // 147456

__global__ __launch_bounds__(256, 1)
void dcls_mma(const float* __restrict__ x, const float* __restrict__ bias,
              float* __restrict__ out) {
    extern __shared__ char smem[];
    const uint32_t sb = smem_u32(smem);

    const int tid  = threadIdx.x;
    const int lane = tid & 31;
    const int warp = tid >> 5;
    const int wco  = warp >> 2;      // 0..1 : co half
    const int r    = warp & 3;       // 0..3 : output row within block

    const int s  = blockIdx.x;       // 0..895
    const int wt = s & 1;
    const int hg = (s >> 1) % 28;
    const int bb = s / 56;
    const int h0 = hg * 4;
    const int w0 = wt * 56;

    // per-lane ldmatrix row offsets
    const int arow = lane & 15;
    const int akh  = (lane >> 4) * 8;
    const uint32_t a_lane_off = (uint32_t)((wco * 64 + arow) * 144 + akh * 2);
    const int bnrow = (lane & 7) + ((lane >> 4) << 3);
    const int bkh   = ((lane >> 3) & 1) * 8;
    const uint32_t b_lane_base = (uint32_t)(bnrow * 144 + bkh * 2);

    float acc[4][7][4];
    #pragma unroll
    for (int i = 0; i < 4; i++)
        #pragma unroll
        for (int j = 0; j < 7; j++)
            #pragma unroll
            for (int k = 0; k < 4; k++) acc[i][j][k] = 0.f;

    for (int c = 0; c < 2; c++) {
        const int ci0 = c * 64;
        __syncthreads();   // all readers of xs/A from previous chunk are done

        // ---- stage x tile: 12 rows x 64 w x 64 ci, f16, zero-padded halo ----
        for (int ci = 0; ci < 64; ci++) {
            const float* xrow = x + (size_t)(bb * 128 + ci0 + ci) * 12544;
            #pragma unroll
            for (int q = 0; q < 3; q++) {
                int p  = tid + q * 256;          // 0..767
                int hh = p >> 6, wl = p & 63;
                int gh = h0 - 4 + hh, gw = w0 - 4 + wl;
                float v = 0.f;
                if ((unsigned)gh < 112u && (unsigned)gw < 112u)
                    v = xrow[gh * 112 + gw];
                *(__half*)(smem + p * XS_STRIDE + ci * 2) = __float2half_rn(v);
            }
        }
        // ---- stage A for tap 0 into buf 0 ----
        {
            const uint4* g = g_K2h4 + (ci0 >> 3);
            #pragma unroll
            for (int k = 0; k < 4; k++) {
                int u = tid + k * 256;           // 0..1023
                int co = u >> 3, c8 = u & 7;
                uint4 v = g[co * 16 + c8];
                *(uint4*)(smem + A_OFF + co * 144 + c8 * 16) = v;
            }
        }
        __syncthreads();

        for (int tap = 0; tap < 81; tap++) {
            // prefetch next tap's A slice (L2-resident) into registers
            uint4 pref[4];
            if (tap < 80) {
                const uint4* g = g_K2h4 + (size_t)(tap + 1) * 2048 + (ci0 >> 3);
                #pragma unroll
                for (int k = 0; k < 4; k++) {
                    int u = tid + k * 256;
                    pref[k] = g[(u >> 3) * 16 + (u & 7)];
                }
            }

            const int dh = tap / 9, dw = tap - dh * 9;
            const uint32_t abase = sb + A_OFF + (tap & 1) * A_BYTES + a_lane_off;
            const uint32_t bbase = sb + (uint32_t)(((r + dh) * 64 + dw) * 144) + b_lane_base;

            #pragma unroll
            for (int kk = 0; kk < 4; kk++) {
                uint32_t a[4][4];
                #pragma unroll
                for (int i = 0; i < 4; i++)
                    LDSM4(a[i], abase + i * 2304 + kk * 32);

                #pragma unroll
                for (int jj = 0; jj < 3; jj++) {
                    uint32_t b[4];
                    LDSM4(b, bbase + jj * 2304 + kk * 32);
                    #pragma unroll
                    for (int i = 0; i < 4; i++) {
                        HMMA(acc[i][2 * jj],     a[i], b[0], b[1]);
                        HMMA(acc[i][2 * jj + 1], a[i], b[2], b[3]);
                    }
                }
                {
                    uint32_t b[2];
                    LDSM2(b, bbase + 3 * 2304 + kk * 32);
                    #pragma unroll
                    for (int i = 0; i < 4; i++)
                        HMMA(acc[i][6], a[i], b[0], b[1]);
                }
            }

            if (tap < 80) {
                char* A1 = smem + A_OFF + ((tap + 1) & 1) * A_BYTES;
                #pragma unroll
                for (int k = 0; k < 4; k++) {
                    int u = tid + k * 256;
                    *(uint4*)(A1 + (u >> 3) * 144 + (u & 7) * 16) = pref[k];
                }
            }
            __syncthreads();
        }
    }

    // ================= epilogue: + bias, float2 stores =================
    const int gq = lane >> 2, tq = lane & 3;
    #pragma unroll
    for (int i = 0; i < 4; i++) {
        const int co = wco * 64 + i * 16 + gq;
        const float b0 = bias[co];
        const float b1 = bias[co + 8];
        const size_t o0 = ((size_t)(bb * 128 + co) * 112 + (h0 + r)) * 112 + w0;
        const size_t o1 = o0 + (size_t)8 * 12544;
        #pragma unroll
        for (int j = 0; j < 7; j++) {
            const int wcol = j * 8 + tq * 2;
            *(float2*)(out + o0 + wcol) = make_float2(acc[i][j][0] + b0, acc[i][j][1] + b0);
            *(float2*)(out + o1 + wcol) = make_float2(acc[i][j][2] + b1, acc[i][j][3] + b1);
        }
    }
}

// ================= launch =================
extern "C" void kernel_launch(void* const* d_in, const int* in_sizes, int n_in,
                              void* d_out, int out_size) {
    const float* x      = (const float*)d_in[0];
    const float* weight = (const float*)d_in[1];
    const float* P      = (const float*)d_in[2];
    const float* bias   = (const float*)d_in[3];
    float* out = (float*)d_out;

    build_K<<<128, 128>>>(weight, P);

    cudaFuncSetAttribute(dcls_mma, cudaFuncAttributeMaxDynamicSharedMemorySize, SMEM_TOTAL);
    dcls_mma<<<896, 256, SMEM_TOTAL>>>(x, bias, out);
}